// round 1
// baseline (speedup 1.0000x reference)
#include <cuda_runtime.h>
#include <cstdint>
#include <cstddef>

// Butterfly transform: B=8192 rows, N=4096, 12 stages, increasing stride.
// out[lo] = t00*x[lo] + t01*x[hi]; out[hi] = t10*x[lo] + t11*x[hi]
// twiddle layout: (12, 2048, 2, 2) float32; q = d*stride + j for pair
// (lo = d*2*stride + j, hi = lo + stride).
//
// Strategy: CTA of 512 threads processes 12 rows (6 row-pairs packed as float2).
// 4 phases of 3 stages each, done in registers; each thread owns 8 elements at
// stride 8^phase. Only 3 smem exchanges. Twiddles (12 float4/thread/phase) are
// held in registers across the row-pair loop to amortize L2 traffic.
// Smem index swizzle makes all 4 phase access patterns bank-conflict-free.

namespace {
constexpr int kN       = 4096;
constexpr int kBatch   = 8192;
constexpr int kThreads = 512;
constexpr int kRows    = 12;
constexpr int kPairs   = kRows / 2;                         // 6
constexpr int kGrid    = (kBatch + kRows - 1) / kRows;      // 683
constexpr int kSmem    = kPairs * kN * (int)sizeof(float2); // 196608 B
}

// Bank swizzle at float2 (8B) granularity. Keeps index within its 16-aligned
// block, bijective. Conflict-free (verified over GF2) for element patterns
// i = base + s*m with s in {1,8,64,512}.
__device__ __forceinline__ int swz(int i) {
    return (i & ~15) | ((i & 15) ^ ((i >> 4) & 7) ^ ((i >> 3) & 8));
}

// One 2x2 butterfly applied to two rows packed in float2 lanes.
__device__ __forceinline__ void bfly(float2& x0, float2& x1, const float4 tm) {
    float2 y0, y1;
    y0.x = __fmaf_rn(tm.y, x1.x, tm.x * x0.x);
    y0.y = __fmaf_rn(tm.y, x1.y, tm.x * x0.y);
    y1.x = __fmaf_rn(tm.w, x1.x, tm.z * x0.x);
    y1.y = __fmaf_rn(tm.w, x1.y, tm.z * x0.y);
    x0 = y0;
    x1 = y1;
}

// Three in-register substages over 8 owned elements (local strides 1,2,4).
__device__ __forceinline__ void substages(float2 v[8], const float4 twr[3][4]) {
    // u = 0: pairs (0,1)(2,3)(4,5)(6,7)
    bfly(v[0], v[1], twr[0][0]); bfly(v[2], v[3], twr[0][1]);
    bfly(v[4], v[5], twr[0][2]); bfly(v[6], v[7], twr[0][3]);
    // u = 1: pairs (0,2)(1,3)(4,6)(5,7)
    bfly(v[0], v[2], twr[1][0]); bfly(v[1], v[3], twr[1][1]);
    bfly(v[4], v[6], twr[1][2]); bfly(v[5], v[7], twr[1][3]);
    // u = 2: pairs (0,4)(1,5)(2,6)(3,7)
    bfly(v[0], v[4], twr[2][0]); bfly(v[1], v[5], twr[2][1]);
    bfly(v[2], v[6], twr[2][2]); bfly(v[3], v[7], twr[2][3]);
}

__global__ void __launch_bounds__(kThreads, 1)
butterfly_kernel(const float* __restrict__ x,
                 const float* __restrict__ tw,
                 float* __restrict__ out) {
    extern __shared__ float2 buf[];  // kPairs * kN float2
    const int t    = threadIdx.x;
    const int row0 = blockIdx.x * kRows;
    const int npairs = min(kPairs, (kBatch - row0) >> 1);
    const float4* tw4 = reinterpret_cast<const float4*>(tw);

    // ---------------- Phase 0: stages 0..2 (strides 1,2,4) ----------------
    {
        // ownership: s=1, b=t, c=0 -> elements 8t..8t+7
        float4 twr[3][4];
        #pragma unroll
        for (int u = 0; u < 3; ++u)
            #pragma unroll
            for (int pm = 0; pm < 4; ++pm)
                twr[u][pm] = tw4[u * 2048 + 4 * t + pm];
        int off[8];
        #pragma unroll
        for (int m = 0; m < 8; ++m) off[m] = swz(8 * t + m);

        for (int p = 0; p < npairs; ++p) {
            const float4* xa =
                reinterpret_cast<const float4*>(x + (size_t)(row0 + 2 * p) * kN);
            const float4* xb =
                reinterpret_cast<const float4*>(x + (size_t)(row0 + 2 * p + 1) * kN);
            const float4 a0 = xa[2 * t], a1 = xa[2 * t + 1];
            const float4 b0 = xb[2 * t], b1 = xb[2 * t + 1];
            float2 v[8];
            v[0] = make_float2(a0.x, b0.x); v[1] = make_float2(a0.y, b0.y);
            v[2] = make_float2(a0.z, b0.z); v[3] = make_float2(a0.w, b0.w);
            v[4] = make_float2(a1.x, b1.x); v[5] = make_float2(a1.y, b1.y);
            v[6] = make_float2(a1.z, b1.z); v[7] = make_float2(a1.w, b1.w);

            substages(v, twr);

            float2* B = buf + p * kN;
            #pragma unroll
            for (int m = 0; m < 8; ++m) B[off[m]] = v[m];
        }
    }
    __syncthreads();

    // ------------- Phases 1,2: stages 3..8 (strides 8..256), smem ---------
    #pragma unroll
    for (int ph = 1; ph <= 2; ++ph) {
        const int ls = 3 * ph;          // log2(s): 3 or 6
        const int s  = 1 << ls;         // 8 or 64
        const int b  = t >> ls;
        const int c  = t & (s - 1);

        float4 twr[3][4];
        #pragma unroll
        for (int u = 0; u < 3; ++u)
            #pragma unroll
            for (int pm = 0; pm < 4; ++pm)
                twr[u][pm] = tw4[(3 * ph + u) * 2048 + s * (4 * b + pm) + c];
        int off[8];
        #pragma unroll
        for (int m = 0; m < 8; ++m) off[m] = swz(b * 8 * s + c + s * m);

        for (int p = 0; p < npairs; ++p) {
            float2* B = buf + p * kN;
            float2 v[8];
            #pragma unroll
            for (int m = 0; m < 8; ++m) v[m] = B[off[m]];

            substages(v, twr);

            #pragma unroll
            for (int m = 0; m < 8; ++m) B[off[m]] = v[m];
        }
        __syncthreads();
    }

    // ------------- Phase 3: stages 9..11 (strides 512..2048) -> out -------
    {
        const int s = 512;  // b = 0, c = t
        float4 twr[3][4];
        #pragma unroll
        for (int u = 0; u < 3; ++u)
            #pragma unroll
            for (int pm = 0; pm < 4; ++pm)
                twr[u][pm] = tw4[(9 + u) * 2048 + s * pm + t];
        int off[8];
        #pragma unroll
        for (int m = 0; m < 8; ++m) off[m] = swz(t + s * m);

        for (int p = 0; p < npairs; ++p) {
            float2* B = buf + p * kN;
            float2 v[8];
            #pragma unroll
            for (int m = 0; m < 8; ++m) v[m] = B[off[m]];

            substages(v, twr);

            float* oa = out + (size_t)(row0 + 2 * p) * kN;
            float* ob = out + (size_t)(row0 + 2 * p + 1) * kN;
            #pragma unroll
            for (int m = 0; m < 8; ++m) {
                oa[t + s * m] = v[m].x;   // warp-contiguous 4B stores
                ob[t + s * m] = v[m].y;
            }
        }
    }
}

extern "C" void kernel_launch(void* const* d_in, const int* in_sizes, int n_in,
                              void* d_out, int out_size) {
    const float* x  = (const float*)d_in[0];   // (8192, 4096) fp32
    const float* tw = (const float*)d_in[1];   // (1,1,12,2048,2,2) fp32
    float* out      = (float*)d_out;           // (8192, 4096) fp32

    cudaFuncSetAttribute(butterfly_kernel,
                         cudaFuncAttributeMaxDynamicSharedMemorySize, kSmem);
    butterfly_kernel<<<kGrid, kThreads, kSmem>>>(x, tw, out);
}

// round 2
// speedup vs baseline: 1.0688x; 1.0688x over previous
#include <cuda_runtime.h>
#include <cstdint>
#include <cstddef>

// Butterfly transform: B=8192 rows, N=4096, 12 stages, increasing stride.
// CTA = 512 threads, 12 rows (6 float2-packed row pairs), 192KB smem,
// 4 register phases of 3 stages, 3 smem exchanges, conflict-free swizzle.
// R2 change: compile-time NPAIRS (6 main / 4 tail) + full unrolling for ILP.

namespace {
constexpr int kN       = 4096;
constexpr int kBatch   = 8192;
constexpr int kThreads = 512;
constexpr int kRows    = 12;
constexpr int kPairs   = kRows / 2;                         // 6
constexpr int kGrid    = 683;                               // 682 full + 1 tail (4 pairs)
constexpr int kSmem    = kPairs * kN * (int)sizeof(float2); // 196608 B
}

// Bank swizzle at float2 (8B) granularity; bijective within 16-blocks;
// conflict-free for element patterns i = base + s*m, s in {1,8,64,512}.
__device__ __forceinline__ int swz(int i) {
    return (i & ~15) | ((i & 15) ^ ((i >> 4) & 7) ^ ((i >> 3) & 8));
}

// One 2x2 butterfly applied to two rows packed in float2 lanes.
__device__ __forceinline__ void bfly(float2& x0, float2& x1, const float4 tm) {
    float2 y0, y1;
    y0.x = __fmaf_rn(tm.y, x1.x, tm.x * x0.x);
    y0.y = __fmaf_rn(tm.y, x1.y, tm.x * x0.y);
    y1.x = __fmaf_rn(tm.w, x1.x, tm.z * x0.x);
    y1.y = __fmaf_rn(tm.w, x1.y, tm.z * x0.y);
    x0 = y0;
    x1 = y1;
}

// Three in-register substages over 8 owned elements (local strides 1,2,4).
__device__ __forceinline__ void substages(float2 v[8], const float4 twr[3][4]) {
    bfly(v[0], v[1], twr[0][0]); bfly(v[2], v[3], twr[0][1]);
    bfly(v[4], v[5], twr[0][2]); bfly(v[6], v[7], twr[0][3]);
    bfly(v[0], v[2], twr[1][0]); bfly(v[1], v[3], twr[1][1]);
    bfly(v[4], v[6], twr[1][2]); bfly(v[5], v[7], twr[1][3]);
    bfly(v[0], v[4], twr[2][0]); bfly(v[1], v[5], twr[2][1]);
    bfly(v[2], v[6], twr[2][2]); bfly(v[3], v[7], twr[2][3]);
}

template <int NPAIRS>
__device__ __forceinline__ void bf_body(const float* __restrict__ x,
                                        const float* __restrict__ tw,
                                        float* __restrict__ out,
                                        int row0, float2* buf) {
    const int t = threadIdx.x;
    const float4* tw4 = reinterpret_cast<const float4*>(tw);

    // ---------------- Phase 0: stages 0..2 (strides 1,2,4) ----------------
    {
        float4 twr[3][4];
        #pragma unroll
        for (int u = 0; u < 3; ++u)
            #pragma unroll
            for (int pm = 0; pm < 4; ++pm)
                twr[u][pm] = tw4[u * 2048 + 4 * t + pm];
        int off[8];
        #pragma unroll
        for (int m = 0; m < 8; ++m) off[m] = swz(8 * t + m);

        #pragma unroll
        for (int p = 0; p < NPAIRS; ++p) {
            const float4* xa =
                reinterpret_cast<const float4*>(x + (size_t)(row0 + 2 * p) * kN);
            const float4* xb =
                reinterpret_cast<const float4*>(x + (size_t)(row0 + 2 * p + 1) * kN);
            const float4 a0 = xa[2 * t], a1 = xa[2 * t + 1];
            const float4 b0 = xb[2 * t], b1 = xb[2 * t + 1];
            float2 v[8];
            v[0] = make_float2(a0.x, b0.x); v[1] = make_float2(a0.y, b0.y);
            v[2] = make_float2(a0.z, b0.z); v[3] = make_float2(a0.w, b0.w);
            v[4] = make_float2(a1.x, b1.x); v[5] = make_float2(a1.y, b1.y);
            v[6] = make_float2(a1.z, b1.z); v[7] = make_float2(a1.w, b1.w);

            substages(v, twr);

            float2* B = buf + p * kN;
            #pragma unroll
            for (int m = 0; m < 8; ++m) B[off[m]] = v[m];
        }
    }
    __syncthreads();

    // ------------- Phases 1,2: stages 3..8 (strides 8..256), smem ---------
    #pragma unroll
    for (int ph = 1; ph <= 2; ++ph) {
        const int ls = 3 * ph;          // 3 or 6
        const int s  = 1 << ls;         // 8 or 64
        const int b  = t >> ls;
        const int c  = t & (s - 1);

        float4 twr[3][4];
        #pragma unroll
        for (int u = 0; u < 3; ++u)
            #pragma unroll
            for (int pm = 0; pm < 4; ++pm)
                twr[u][pm] = tw4[(3 * ph + u) * 2048 + s * (4 * b + pm) + c];
        int off[8];
        #pragma unroll
        for (int m = 0; m < 8; ++m) off[m] = swz(b * 8 * s + c + s * m);

        #pragma unroll
        for (int p = 0; p < NPAIRS; ++p) {
            float2* B = buf + p * kN;
            float2 v[8];
            #pragma unroll
            for (int m = 0; m < 8; ++m) v[m] = B[off[m]];

            substages(v, twr);

            #pragma unroll
            for (int m = 0; m < 8; ++m) B[off[m]] = v[m];
        }
        __syncthreads();
    }

    // ------------- Phase 3: stages 9..11 (strides 512..2048) -> out -------
    {
        const int s = 512;  // b = 0, c = t
        float4 twr[3][4];
        #pragma unroll
        for (int u = 0; u < 3; ++u)
            #pragma unroll
            for (int pm = 0; pm < 4; ++pm)
                twr[u][pm] = tw4[(9 + u) * 2048 + s * pm + t];
        int off[8];
        #pragma unroll
        for (int m = 0; m < 8; ++m) off[m] = swz(t + s * m);

        #pragma unroll
        for (int p = 0; p < NPAIRS; ++p) {
            float2* B = buf + p * kN;
            float2 v[8];
            #pragma unroll
            for (int m = 0; m < 8; ++m) v[m] = B[off[m]];

            substages(v, twr);

            float* oa = out + (size_t)(row0 + 2 * p) * kN;
            float* ob = out + (size_t)(row0 + 2 * p + 1) * kN;
            #pragma unroll
            for (int m = 0; m < 8; ++m) {
                oa[t + s * m] = v[m].x;   // warp-contiguous 4B stores
                ob[t + s * m] = v[m].y;
            }
        }
    }
}

__global__ void __launch_bounds__(kThreads, 1)
butterfly_kernel(const float* __restrict__ x,
                 const float* __restrict__ tw,
                 float* __restrict__ out) {
    extern __shared__ float2 buf[];
    const int row0 = blockIdx.x * kRows;
    if (blockIdx.x < kGrid - 1) {
        bf_body<6>(x, tw, out, row0, buf);   // rows 0..8183
    } else {
        bf_body<4>(x, tw, out, row0, buf);   // rows 8184..8191 (8 rows)
    }
}

extern "C" void kernel_launch(void* const* d_in, const int* in_sizes, int n_in,
                              void* d_out, int out_size) {
    const float* x  = (const float*)d_in[0];   // (8192, 4096) fp32
    const float* tw = (const float*)d_in[1];   // (1,1,12,2048,2,2) fp32
    float* out      = (float*)d_out;           // (8192, 4096) fp32

    cudaFuncSetAttribute(butterfly_kernel,
                         cudaFuncAttributeMaxDynamicSharedMemorySize, kSmem);
    butterfly_kernel<<<kGrid, kThreads, kSmem>>>(x, tw, out);
}